// round 15
// baseline (speedup 1.0000x reference)
#include <cuda_runtime.h>
#include <cstdint>

// GRU_12962211299468 : B=65536, T=9, I=57, H=2, O=1, fp32
// Round 15: ONE kernel, warp owns 4 WHOLE batch elements (36 rows = 2052
// floats = 8208 B, 16B-aligned -> per-warp cp.async works).
//   stage:   warp-private cp.async of its 513 16B chunks (self-paced)
//   project: pass1 lane=row (rows 0-31), pass2 lanes 0-3 (rows 32-35);
//            FFMA2 packed gate pairs, weights pre-packed in smem
//   recur:   lanes 0-3 run the 4 batches' 9-step recurrence from warp smem
// No block barrier in the hot path, no gx scratch (-29.4 MB), no 2nd launch
// (K2 was invariant ~10.5us across 5 designs -> structural, so eliminated).

#define T_STEPS 9
#define I_DIM   57
#define B_TOT   65536
#define BPW     4                        // whole batches per warp
#define RPW     (BPW * T_STEPS)          // 36 rows per warp
#define WTILE   (RPW * I_DIM)            // 2052 floats = 8208 B (16B-aligned)
#define WV4     (WTILE / 4)              // 513 chunks
#define CWARPS  4
#define NTHR    (CWARPS * 32)            // 128
#define GRID    (B_TOT / (BPW * CWARPS)) // 4096
#define PROW    120                      // packed-weight row: 60 pairs
#define SGXROW  57                       // per-batch gate row stride (odd)

typedef unsigned long long u64;

__device__ __forceinline__ uint32_t s2u(const void* p) {
    uint32_t a;
    asm("{ .reg .u64 t; cvta.to.shared.u64 t, %1; cvt.u32.u64 %0, t; }"
        : "=r"(a) : "l"(p));
    return a;
}
__device__ __forceinline__ void cp16(uint32_t dst, const void* src) {
    asm volatile("cp.async.cg.shared.global [%0], [%1], 16;"
                 :: "r"(dst), "l"(src) : "memory");
}
__device__ __forceinline__ void cp_commit() {
    asm volatile("cp.async.commit_group;" ::: "memory");
}
__device__ __forceinline__ void cp_wait0() {
    asm volatile("cp.async.wait_group 0;" ::: "memory");
}
__device__ __forceinline__ u64 pack2(float lo, float hi) {
    u64 r;
    asm("mov.b64 %0, {%1, %2};" : "=l"(r) : "f"(lo), "f"(hi));
    return r;
}
__device__ __forceinline__ void unpack2(float& lo, float& hi, u64 v) {
    asm("mov.b64 {%0, %1}, %2;" : "=f"(lo), "=f"(hi) : "l"(v));
}
__device__ __forceinline__ void fma2(u64& d, u64 a, u64 b) {
    asm("fma.rn.f32x2 %0, %1, %2, %0;" : "+l"(d) : "l"(a), "l"(b));
}

__device__ __forceinline__ float sigf(float v) {
    return 1.0f / (1.0f + __expf(-v));
}
__device__ __forceinline__ float tanh_ex(float v) {
    return 1.0f - 2.0f / (__expf(2.0f * v) + 1.0f);
}

// 6x57 dot products for one row, FFMA2-packed. Writes g0..g5.
__device__ __forceinline__ void project_row(
    const float* __restrict__ row, const float* __restrict__ swp,
    u64 bi01, u64 bi23, u64 bi45,
    float& g0, float& g1, float& g2, float& g3, float& g4, float& g5)
{
    u64 a01 = bi01, a23 = bi23, a45 = bi45;
#pragma unroll
    for (int c = 0; c < 14; ++c) {
        float x0 = row[4 * c + 0];
        float x1 = row[4 * c + 1];
        float x2 = row[4 * c + 2];
        float x3 = row[4 * c + 3];
        u64 xx0 = pack2(x0, x0);
        u64 xx1 = pack2(x1, x1);
        u64 xx2 = pack2(x2, x2);
        u64 xx3 = pack2(x3, x3);
        {
            const float4* wp = reinterpret_cast<const float4*>(&swp[0 * PROW + 8 * c]);
            float4 wa = wp[0], wb = wp[1];
            fma2(a01, pack2(wa.x, wa.y), xx0);
            fma2(a01, pack2(wa.z, wa.w), xx1);
            fma2(a01, pack2(wb.x, wb.y), xx2);
            fma2(a01, pack2(wb.z, wb.w), xx3);
        }
        {
            const float4* wp = reinterpret_cast<const float4*>(&swp[1 * PROW + 8 * c]);
            float4 wa = wp[0], wb = wp[1];
            fma2(a23, pack2(wa.x, wa.y), xx0);
            fma2(a23, pack2(wa.z, wa.w), xx1);
            fma2(a23, pack2(wb.x, wb.y), xx2);
            fma2(a23, pack2(wb.z, wb.w), xx3);
        }
        {
            const float4* wp = reinterpret_cast<const float4*>(&swp[2 * PROW + 8 * c]);
            float4 wa = wp[0], wb = wp[1];
            fma2(a45, pack2(wa.x, wa.y), xx0);
            fma2(a45, pack2(wa.z, wa.w), xx1);
            fma2(a45, pack2(wb.x, wb.y), xx2);
            fma2(a45, pack2(wb.z, wb.w), xx3);
        }
    }
    {   // tail i = 56
        float xs = row[56];
        u64 xx = pack2(xs, xs);
        fma2(a01, *reinterpret_cast<const u64*>(&swp[0 * PROW + 112]), xx);
        fma2(a23, *reinterpret_cast<const u64*>(&swp[1 * PROW + 112]), xx);
        fma2(a45, *reinterpret_cast<const u64*>(&swp[2 * PROW + 112]), xx);
    }
    unpack2(g0, g1, a01);
    unpack2(g2, g3, a23);
    unpack2(g4, g5, a45);
}

__global__ __launch_bounds__(NTHR, 6) void gru_one(
    const float* __restrict__ x,
    const float* __restrict__ Wih,   // [6,57]
    const float* __restrict__ Whh,   // [6,2]
    const float* __restrict__ bih,   // [6]
    const float* __restrict__ bhh,   // [6]
    const float* __restrict__ fcw,   // [2]
    const float* __restrict__ fcb,   // [1]
    float* __restrict__ out)         // [B]
{
    __shared__ __align__(16) float sx[CWARPS][WTILE];        // 32832 B
    __shared__ float sgx[CWARPS][BPW * SGXROW];              //  3648 B
    __shared__ __align__(16) float swp[3 * PROW];            //  1440 B

    const int tid  = threadIdx.x;
    const int wid  = tid >> 5;
    const int lane = tid & 31;
    const int wg   = blockIdx.x * CWARPS + wid;   // global warp id

    // ---- kick this warp's tile load first (overlaps weight packing) ----
    {
        const float4* src = reinterpret_cast<const float4*>(x) + (size_t)wg * WV4;
        const uint32_t sb = s2u(&sx[wid][0]);
#pragma unroll
        for (int k = 0; k < 17; ++k) {
            int j = lane + 32 * k;
            if (j < WV4) cp16(sb + 16u * (uint32_t)j, src + j);
        }
    }
    cp_commit();

    // ---- pack W_ih pairwise into smem ----
    for (int j = tid; j < 3 * (PROW / 2); j += NTHR) {
        int p = j / (PROW / 2);
        int i = j - p * (PROW / 2);
        float a = 0.0f, b = 0.0f;
        if (i < I_DIM) {
            a = Wih[(2 * p) * I_DIM + i];
            b = Wih[(2 * p + 1) * I_DIM + i];
        }
        swp[p * PROW + 2 * i]     = a;
        swp[p * PROW + 2 * i + 1] = b;
    }
    __syncthreads();          // swp visible (once, outside hot path)

    const u64 bi01 = pack2(bih[0], bih[1]);
    const u64 bi23 = pack2(bih[2], bih[3]);
    const u64 bi45 = pack2(bih[4], bih[5]);

    cp_wait0();               // this warp's tile complete
    __syncwarp();

    // ---- pass 1: lane = row 0..31 ----
    {
        const int j  = lane;                 // row in warp tile
        const int bl = j / 9;                // batch local 0..3
        const int tt = j - 9 * bl;
        float g0, g1, g2, g3, g4, g5;
        project_row(&sx[wid][j * I_DIM], swp, bi01, bi23, bi45,
                    g0, g1, g2, g3, g4, g5);
        float* gq = &sgx[wid][bl * SGXROW + 6 * tt];
        gq[0] = g0; gq[1] = g1; gq[2] = g2;
        gq[3] = g3; gq[4] = g4; gq[5] = g5;
    }
    // ---- pass 2: lanes 0-3 handle rows 32-35 ----
    if (lane < 4) {
        const int j  = 32 + lane;
        const int bl = j / 9;                // 3
        const int tt = j - 9 * bl;           // 5..8
        float g0, g1, g2, g3, g4, g5;
        project_row(&sx[wid][j * I_DIM], swp, bi01, bi23, bi45,
                    g0, g1, g2, g3, g4, g5);
        float* gq = &sgx[wid][bl * SGXROW + 6 * tt];
        gq[0] = g0; gq[1] = g1; gq[2] = g2;
        gq[3] = g3; gq[4] = g4; gq[5] = g5;
    }
    __syncwarp();

    // ---- recurrence + FC: lanes 0-3, one batch each ----
    if (lane < 4) {
        const float w00 = Whh[0],  w01 = Whh[1];
        const float w10 = Whh[2],  w11 = Whh[3];
        const float w20 = Whh[4],  w21 = Whh[5];
        const float w30 = Whh[6],  w31 = Whh[7];
        const float w40 = Whh[8],  w41 = Whh[9];
        const float w50 = Whh[10], w51 = Whh[11];
        const float bh0 = bhh[0], bh1 = bhh[1], bh2 = bhh[2];
        const float bh3 = bhh[3], bh4 = bhh[4], bh5 = bhh[5];

        const float* gp = &sgx[wid][lane * SGXROW];   // stride 57: conflict-free
        float h0 = 0.0f, h1 = 0.0f;

#pragma unroll
        for (int t = 0; t < T_STEPS; ++t) {
            float q0 = gp[6 * t + 0];
            float q1 = gp[6 * t + 1];
            float q2 = gp[6 * t + 2];
            float q3 = gp[6 * t + 3];
            float q4 = gp[6 * t + 4];
            float q5 = gp[6 * t + 5];

            float a0 = w00 * h0 + w01 * h1 + bh0;
            float a1 = w10 * h0 + w11 * h1 + bh1;
            float a2 = w20 * h0 + w21 * h1 + bh2;
            float a3 = w30 * h0 + w31 * h1 + bh3;
            float a4 = w40 * h0 + w41 * h1 + bh4;
            float a5 = w50 * h0 + w51 * h1 + bh5;

            float r0 = sigf(q0 + a0);
            float r1 = sigf(q1 + a1);
            float z0 = sigf(q2 + a2);
            float z1 = sigf(q3 + a3);
            float n0 = tanh_ex(q4 + r0 * a4);
            float n1 = tanh_ex(q5 + r1 * a5);

            h0 = (1.0f - z0) * n0 + z0 * h0;
            h1 = (1.0f - z1) * n1 + z1 * h1;
        }

        out[wg * BPW + lane] = fcw[0] * h0 + fcw[1] * h1 + fcb[0];
    }
}

extern "C" void kernel_launch(void* const* d_in, const int* in_sizes, int n_in,
                              void* d_out, int out_size) {
    const float* x   = (const float*)d_in[0];
    const float* Wih = (const float*)d_in[1];
    const float* Whh = (const float*)d_in[2];
    const float* bih = (const float*)d_in[3];
    const float* bhh = (const float*)d_in[4];
    const float* fcw = (const float*)d_in[5];
    const float* fcb = (const float*)d_in[6];
    float* out = (float*)d_out;

    (void)in_sizes; (void)n_in; (void)out_size;

    gru_one<<<GRID, NTHR>>>(x, Wih, Whh, bih, bhh, fcw, fcb, out);
}

// round 16
// speedup vs baseline: 4.4371x; 4.4371x over previous
#include <cuda_runtime.h>
#include <cstdint>

// GRU_12962211299468 : B=65536, T=9, I=57, H=2, O=1, fp32
// Round 16: R14 base, K1 staging switched from 456 LDGSTS/warp to ONE
// cp.async.bulk (UBLKCP) per warp + per-warp mbarrier. Theory: K1 was
// LDGSTS-issue-bound (8.4M ops ~ 28us at ~1/cyc/SM == measured K1 time).
// K2 = R13's coalesced LDG.128 version (best of the ~10.3us family).

#define T_STEPS 9
#define I_DIM   57
#define B_TOT   65536
#define NROWS_T (B_TOT * T_STEPS)       // 589824 rows
#define RPW     32                      // rows per warp
#define RPW_FLT (RPW * I_DIM)           // 1824 floats per warp tile
#define TILE_B  (RPW_FLT * 4)           // 7296 bytes (16B-aligned multiple)
#define WARPS_K1 (NROWS_T / RPW)        // 18432
#define CWARPS  4
#define K1_THR  (CWARPS * 32)           // 128
#define K1_GRID (WARPS_K1 / CWARPS)     // 4608
#define NCHUNK  14                      // ceil(54/4) gate chunks
#define B4      (B_TOT * 4)             // floats per chunk plane
#define PROW    120                     // packed-weight row: 60 pairs

__device__ __align__(16) float g_gx[(size_t)NCHUNK * B4];   // 14.7 MB scratch

typedef unsigned long long u64;

__device__ __forceinline__ uint32_t s2u(const void* p) {
    uint32_t a;
    asm("{ .reg .u64 t; cvta.to.shared.u64 t, %1; cvt.u32.u64 %0, t; }"
        : "=r"(a) : "l"(p));
    return a;
}
__device__ __forceinline__ void mbar_init(uint32_t addr, uint32_t cnt) {
    asm volatile("mbarrier.init.shared.b64 [%0], %1;" :: "r"(addr), "r"(cnt) : "memory");
}
__device__ __forceinline__ void mbar_expect_tx(uint32_t addr, uint32_t bytes) {
    asm volatile("mbarrier.arrive.expect_tx.shared.b64 _, [%0], %1;"
                 :: "r"(addr), "r"(bytes) : "memory");
}
__device__ __forceinline__ void mbar_wait(uint32_t addr, uint32_t phase) {
    asm volatile(
        "{\n\t"
        ".reg .pred P;\n\t"
        "WL%=:\n\t"
        "mbarrier.try_wait.parity.acquire.cta.shared::cta.b64 P, [%0], %1, 0x989680;\n\t"
        "@!P bra WL%=;\n\t"
        "}"
        :: "r"(addr), "r"(phase) : "memory");
}
__device__ __forceinline__ void tma_bulk(uint32_t dst_smem, const void* src,
                                         uint32_t bytes, uint32_t mbar_addr) {
    asm volatile(
        "cp.async.bulk.shared::cta.global.mbarrier::complete_tx::bytes [%0], [%1], %2, [%3];"
        :: "r"(dst_smem), "l"(src), "r"(bytes), "r"(mbar_addr) : "memory");
}
__device__ __forceinline__ u64 pack2(float lo, float hi) {
    u64 r;
    asm("mov.b64 %0, {%1, %2};" : "=l"(r) : "f"(lo), "f"(hi));
    return r;
}
__device__ __forceinline__ void unpack2(float& lo, float& hi, u64 v) {
    asm("mov.b64 {%0, %1}, %2;" : "=f"(lo), "=f"(hi) : "l"(v));
}
__device__ __forceinline__ void fma2(u64& d, u64 a, u64 b) {
    asm("fma.rn.f32x2 %0, %1, %2, %0;" : "+l"(d) : "l"(a), "l"(b));
}

__device__ __forceinline__ float sigf(float v) {
    return 1.0f / (1.0f + __expf(-v));
}
__device__ __forceinline__ float tanh_ex(float v) {
    return 1.0f - 2.0f / (__expf(2.0f * v) + 1.0f);
}

// ---------------------------------------------------------------- K1 ----
__global__ __launch_bounds__(K1_THR, 7) void gru_proj(
    const float* __restrict__ x,
    const float* __restrict__ Wih,   // [6,57]
    const float* __restrict__ bih)   // [6]
{
    __shared__ __align__(16) float sx[CWARPS][RPW_FLT];  // 4 x 7296 B
    __shared__ __align__(16) float swp[3 * PROW];        // 1440 B
    __shared__ __align__(8) u64 mbar[CWARPS];

    const int tid  = threadIdx.x;
    const int wid  = tid >> 5;
    const int lane = tid & 31;
    const int wg   = blockIdx.x * CWARPS + wid;      // global warp id

    const uint32_t mb = s2u(&mbar[wid]);

    // ---- per-warp: init mbarrier, issue ONE bulk copy for the tile ----
    if (lane == 0) {
        mbar_init(mb, 1);
        asm volatile("fence.proxy.async.shared::cta;" ::: "memory");
        mbar_expect_tx(mb, TILE_B);
        tma_bulk(s2u(&sx[wid][0]),
                 x + (size_t)wg * RPW_FLT, TILE_B, mb);
    }

    // ---- pack W_ih pairwise into smem (overlaps the bulk copies) ----
    for (int j = tid; j < 3 * (PROW / 2); j += K1_THR) {
        int p = j / (PROW / 2);
        int i = j - p * (PROW / 2);
        float a = 0.0f, b = 0.0f;
        if (i < I_DIM) {
            a = Wih[(2 * p) * I_DIM + i];
            b = Wih[(2 * p + 1) * I_DIM + i];
        }
        swp[p * PROW + 2 * i]     = a;
        swp[p * PROW + 2 * i + 1] = b;
    }
    __syncthreads();   // swp visible

    const u64 bi01 = pack2(bih[0], bih[1]);
    const u64 bi23 = pack2(bih[2], bih[3]);
    const u64 bi45 = pack2(bih[4], bih[5]);

    mbar_wait(mb, 0);  // this warp's tile complete (all lanes wait)

    // ---- lane = one row: 3 packed gate-pair dot products (FFMA2) ----
    const float* row = &sx[wid][lane * I_DIM];     // stride 57: conflict-free

    u64 a01 = bi01, a23 = bi23, a45 = bi45;
#pragma unroll
    for (int c = 0; c < 14; ++c) {
        float x0 = row[4 * c + 0];
        float x1 = row[4 * c + 1];
        float x2 = row[4 * c + 2];
        float x3 = row[4 * c + 3];
        u64 xx0 = pack2(x0, x0);
        u64 xx1 = pack2(x1, x1);
        u64 xx2 = pack2(x2, x2);
        u64 xx3 = pack2(x3, x3);
        {
            const float4* wp = reinterpret_cast<const float4*>(&swp[0 * PROW + 8 * c]);
            float4 wa = wp[0], wb = wp[1];
            fma2(a01, pack2(wa.x, wa.y), xx0);
            fma2(a01, pack2(wa.z, wa.w), xx1);
            fma2(a01, pack2(wb.x, wb.y), xx2);
            fma2(a01, pack2(wb.z, wb.w), xx3);
        }
        {
            const float4* wp = reinterpret_cast<const float4*>(&swp[1 * PROW + 8 * c]);
            float4 wa = wp[0], wb = wp[1];
            fma2(a23, pack2(wa.x, wa.y), xx0);
            fma2(a23, pack2(wa.z, wa.w), xx1);
            fma2(a23, pack2(wb.x, wb.y), xx2);
            fma2(a23, pack2(wb.z, wb.w), xx3);
        }
        {
            const float4* wp = reinterpret_cast<const float4*>(&swp[2 * PROW + 8 * c]);
            float4 wa = wp[0], wb = wp[1];
            fma2(a45, pack2(wa.x, wa.y), xx0);
            fma2(a45, pack2(wa.z, wa.w), xx1);
            fma2(a45, pack2(wb.x, wb.y), xx2);
            fma2(a45, pack2(wb.z, wb.w), xx3);
        }
    }
    {   // tail i = 56
        float xs = row[56];
        u64 xx = pack2(xs, xs);
        fma2(a01, *reinterpret_cast<const u64*>(&swp[0 * PROW + 112]), xx);
        fma2(a23, *reinterpret_cast<const u64*>(&swp[1 * PROW + 112]), xx);
        fma2(a45, *reinterpret_cast<const u64*>(&swp[2 * PROW + 112]), xx);
    }

    float g0, g1, g2, g3, g4, g5;
    unpack2(g0, g1, a01);
    unpack2(g2, g3, a23);
    unpack2(g4, g5, a45);

    // ---- scatter to chunk-interleaved gx ----
    const int r = wg * RPW + lane;                 // global row = 9b + t
    const int b = r / 9;
    const int t = r - 9 * b;
    const int c0 = (6 * t) >> 2;
    float* base = &g_gx[(size_t)c0 * B4 + b * 4];
    if ((t & 1) == 0) {
        *reinterpret_cast<float4*>(base) = make_float4(g0, g1, g2, g3);
        *reinterpret_cast<float2*>(base + B4) = make_float2(g4, g5);
    } else {
        *reinterpret_cast<float2*>(base + 2) = make_float2(g0, g1);
        *reinterpret_cast<float4*>(base + B4) = make_float4(g2, g3, g4, g5);
    }
}

// ---------------------------------------------------------------- K2 ----
__global__ __launch_bounds__(128, 1) void gru_recur(
    const float* __restrict__ Whh,   // [6,2]
    const float* __restrict__ bhh,   // [6]
    const float* __restrict__ fcw,   // [2]
    const float* __restrict__ fcb,   // [1]
    float* __restrict__ out)         // [B]
{
    const int b = blockIdx.x * 128 + threadIdx.x;

    // 14 coalesced, independent LDG.128
    float v[NCHUNK * 4];
#pragma unroll
    for (int c = 0; c < NCHUNK; ++c)
        reinterpret_cast<float4*>(v)[c] =
            __ldg(reinterpret_cast<const float4*>(&g_gx[(size_t)c * B4 + b * 4]));

    const float w00 = __ldg(Whh + 0),  w01 = __ldg(Whh + 1);
    const float w10 = __ldg(Whh + 2),  w11 = __ldg(Whh + 3);
    const float w20 = __ldg(Whh + 4),  w21 = __ldg(Whh + 5);
    const float w30 = __ldg(Whh + 6),  w31 = __ldg(Whh + 7);
    const float w40 = __ldg(Whh + 8),  w41 = __ldg(Whh + 9);
    const float w50 = __ldg(Whh + 10), w51 = __ldg(Whh + 11);
    const float bh0 = __ldg(bhh + 0), bh1 = __ldg(bhh + 1), bh2 = __ldg(bhh + 2);
    const float bh3 = __ldg(bhh + 3), bh4 = __ldg(bhh + 4), bh5 = __ldg(bhh + 5);

    float h0 = 0.0f, h1 = 0.0f;
#pragma unroll
    for (int t = 0; t < T_STEPS; ++t) {
        float q0 = v[6 * t + 0];
        float q1 = v[6 * t + 1];
        float q2 = v[6 * t + 2];
        float q3 = v[6 * t + 3];
        float q4 = v[6 * t + 4];
        float q5 = v[6 * t + 5];

        float a0 = w00 * h0 + w01 * h1 + bh0;
        float a1 = w10 * h0 + w11 * h1 + bh1;
        float a2 = w20 * h0 + w21 * h1 + bh2;
        float a3 = w30 * h0 + w31 * h1 + bh3;
        float a4 = w40 * h0 + w41 * h1 + bh4;
        float a5 = w50 * h0 + w51 * h1 + bh5;

        float r0 = sigf(q0 + a0);
        float r1 = sigf(q1 + a1);
        float z0 = sigf(q2 + a2);
        float z1 = sigf(q3 + a3);
        float n0 = tanh_ex(q4 + r0 * a4);
        float n1 = tanh_ex(q5 + r1 * a5);

        h0 = (1.0f - z0) * n0 + z0 * h0;
        h1 = (1.0f - z1) * n1 + z1 * h1;
    }

    out[b] = __ldg(fcw + 0) * h0 + __ldg(fcw + 1) * h1 + __ldg(fcb);
}

extern "C" void kernel_launch(void* const* d_in, const int* in_sizes, int n_in,
                              void* d_out, int out_size) {
    const float* x   = (const float*)d_in[0];
    const float* Wih = (const float*)d_in[1];
    const float* Whh = (const float*)d_in[2];
    const float* bih = (const float*)d_in[3];
    const float* bhh = (const float*)d_in[4];
    const float* fcw = (const float*)d_in[5];
    const float* fcb = (const float*)d_in[6];
    float* out = (float*)d_out;

    (void)in_sizes; (void)n_in; (void)out_size;

    gru_proj<<<K1_GRID, K1_THR>>>(x, Wih, bih);
    gru_recur<<<B_TOT / 128, 128>>>(Whh, bhh, fcw, fcb, out);
}